// round 10
// baseline (speedup 1.0000x reference)
#include <cuda_runtime.h>

// out[b, i] = x[b, i] * diagonal[i]
// x: [8192, 4096] f32, diagonal: [4096] f32, out: [8192, 4096] f32
//
// Column-stationary streaming kernel at the measured GB300 mixed-R/W DRAM
// ceiling. Block-size scaling (256->512) gave the only real win in 6 rounds
// (36.00 -> 35.26us, 6031 GB/s); this extends it to 1024: each CTA owns a
// full 4-row x 16KiB contiguous tile, CTA count halves to 2048.
//  - diagonal loaded once per thread
//  - 4 front-batched independent streaming loads (MLP=4)
//  - evict-streaming hints on both streams
//  - 28 regs -> 2 CTAs/SM = 64 warps (full occupancy)

static constexpr int SIZE     = 4096;
static constexpr int BATCH    = 8192;
static constexpr int SIZE_V4  = SIZE / 4;              // 1024 float4 per row
static constexpr int THREADS  = 1024;                  // one full row per block
static constexpr int ROWS_PER_THREAD = 4;
static constexpr int ROW_BLOCKS = BATCH / ROWS_PER_THREAD;  // 2048

__global__ __launch_bounds__(THREADS)
void diag_scale_kernel(const float4* __restrict__ x,
                       const float4* __restrict__ diag,
                       float4* __restrict__ out)
{
    const int row_block = blockIdx.x;
    const int c = threadIdx.x;                        // float4 column (0..1023)
    const float4 dv = __ldg(&diag[c]);                // ONE diag load per thread

    const long long base =
        (long long)row_block * ROWS_PER_THREAD * SIZE_V4 + c;

    // Front-batched independent loads: MLP = 4
    float4 xv[ROWS_PER_THREAD];
#pragma unroll
    for (int k = 0; k < ROWS_PER_THREAD; k++)
        xv[k] = __ldcs(&x[base + (long long)k * SIZE_V4]);

#pragma unroll
    for (int k = 0; k < ROWS_PER_THREAD; k++) {
        float4 ov;
        ov.x = xv[k].x * dv.x;
        ov.y = xv[k].y * dv.y;
        ov.z = xv[k].z * dv.z;
        ov.w = xv[k].w * dv.w;
        __stcs(&out[base + (long long)k * SIZE_V4], ov);
    }
}

extern "C" void kernel_launch(void* const* d_in, const int* in_sizes, int n_in,
                              void* d_out, int out_size)
{
    const float4* x    = (const float4*)d_in[0];
    const float4* diag = (const float4*)d_in[1];
    float4*       out  = (float4*)d_out;

    diag_scale_kernel<<<ROW_BLOCKS, THREADS>>>(x, diag, out);   // 2048 blocks
}